// round 15
// baseline (speedup 1.0000x reference)
#include <cuda_runtime.h>
#include <cuda_bf16.h>
#include <mma.h>
#include <cstdint>

using namespace nvcuda;
typedef __nv_bfloat16 bf16;

#define NN   20000
#define DEGC 16
#define NE   (NN*DEGC)     // 320000
#define DIMC 128
#define SCALEC 0.25f       // HD^-0.5, HD=16
#define NT4  5000          // edge tiles of 4 nodes / 64 edges

// ---------------- scratch (__device__ globals; no allocation allowed) ----------------
__device__ float g_Q   [NN*DIMC];
__device__ float g_KS  [NN*DIMC];
__device__ float g_V   [NN*DIMC];
__device__ float g_P   [NN*8*DIMC];   // P[n][h][k]
__device__ float g_z   [NN*8*DIMC];   // z[n][h][k]
__device__ float g_aggv[NN*DIMC];     // sum_e a*V[dst]
__device__ float g_WekT[DIMC*DIMC];   // WekT[d][k] = Wek[k][d]*S
// weight slots hi/lo, row-major [k][n]: 0=Wq 1=Wk*S 2=Wv 3=-Wout
__device__ bf16  g_w_hi[4*DIMC*DIMC];
__device__ bf16  g_w_lo[4*DIMC*DIMC];

// ---------------- weight split (4 slots) + WekT transpose (slot 4) ----------------
__global__ void wsplit_kernel(const float* __restrict__ w0, const float* __restrict__ w1,
                              const float* __restrict__ w2, const float* __restrict__ w3,
                              const float* __restrict__ Wek)
{
    int s = blockIdx.y;
    int i = blockIdx.x*256 + threadIdx.x;
    if (s == 4) {
        int d = i>>7, k = i&127;
        g_WekT[i] = Wek[k*128 + d] * SCALEC;
        return;
    }
    const float* srcs[4] = {w0, w1, w2, w3};
    const float  scl [4] = {1.f, SCALEC, 1.f, -1.f};
    float v = srcs[s][i] * scl[s];
    bf16 h = __float2bfloat16(v);
    g_w_hi[s*16384 + i] = h;
    g_w_lo[s*16384 + i] = __float2bfloat16(v - __bfloat162float(h));
}

// ---------------- P precompute v2: block = 64 nodes x 4 heads; 4 CTAs/SM ----------------
#define PK_SMEM (64*128*4 + 64*64*4)
__global__ __launch_bounds__(512) void pkern()
{
    extern __shared__ float smf[];
    float* WT = smf;                 // [dlocal 0..63][k 0..127]
    float* Qs = smf + 8192;          // [node 0..63][dlocal 0..63]

    const int tid = threadIdx.x;
    const int nb0 = blockIdx.x*64;
    const int h0  = blockIdx.y*4;

    for (int i = tid; i < 2048; i += 512)
        *(float4*)(WT + i*4) = *(const float4*)(g_WekT + (size_t)h0*16*128 + i*4);
    for (int i = tid; i < 1024; i += 512) {
        int r = i>>4, c4 = (i&15)*4;
        int n = nb0 + r;
        float4 v = make_float4(0.f,0.f,0.f,0.f);
        if (n < NN) v = *(const float4*)(g_Q + (size_t)n*128 + h0*16 + c4);
        *(float4*)(Qs + r*64 + c4) = v;
    }
    __syncthreads();

    const int w = tid>>5, lane = tid&31;
    const int nl0 = w*4;
    const int k4  = lane*4;

    #pragma unroll
    for (int h = 0; h < 4; h++) {
        float4 acc[4];
        #pragma unroll
        for (int j = 0; j < 4; j++) acc[j] = make_float4(0.f,0.f,0.f,0.f);
        #pragma unroll
        for (int dq = 0; dq < 4; dq++) {
            float4 q4[4];
            #pragma unroll
            for (int j = 0; j < 4; j++)
                q4[j] = *(const float4*)(Qs + (nl0 + j)*64 + h*16 + dq*4);
            #pragma unroll
            for (int dd = 0; dd < 4; dd++) {
                float4 w4 = *(const float4*)(WT + (h*16 + dq*4 + dd)*128 + k4);
                #pragma unroll
                for (int j = 0; j < 4; j++) {
                    float qv = (dd==0) ? q4[j].x : (dd==1) ? q4[j].y : (dd==2) ? q4[j].z : q4[j].w;
                    acc[j].x += qv*w4.x; acc[j].y += qv*w4.y;
                    acc[j].z += qv*w4.z; acc[j].w += qv*w4.w;
                }
            }
        }
        #pragma unroll
        for (int j = 0; j < 4; j++) {
            int n = nb0 + nl0 + j;
            if (n < NN)
                *(float4*)(g_P + ((size_t)n*8 + h0 + h)*128 + k4) = acc[j];
        }
    }
}

// ---------------- multi-slot [M,128]@[128,128] split-bf16 GEMM (QKV) ----------------
#define GEMM_SMEM (4*128*136*2)
__global__ __launch_bounds__(512) void gemm_multi(
    const float* __restrict__ A, int slot0, int nslots,
    float* __restrict__ O0, float* __restrict__ O1, float* __restrict__ O2,
    const float* __restrict__ bias, int M)
{
    extern __shared__ char sm[];
    bf16* sAh = (bf16*)sm;
    bf16* sAl = sAh + 128*136;
    bf16* sWh = sAl + 128*136;
    bf16* sWl = sWh + 128*136;
    float* sC = (float*)(sm + 2*128*136*2);

    const int tid = threadIdx.x;
    const int m0  = blockIdx.x*128;

    for (int i = tid; i < 4096; i += 512) {
        int r = i>>5, c4 = (i&31)*4;
        float4 v = make_float4(0.f,0.f,0.f,0.f);
        if (m0 + r < M) v = *(const float4*)(A + (size_t)(m0+r)*128 + c4);
        bf16 h0=__float2bfloat16(v.x), h1=__float2bfloat16(v.y);
        bf16 h2=__float2bfloat16(v.z), h3=__float2bfloat16(v.w);
        __nv_bfloat162 hh0; hh0.x=h0; hh0.y=h1;
        __nv_bfloat162 hh1; hh1.x=h2; hh1.y=h3;
        *(__nv_bfloat162*)(sAh + r*136 + c4)     = hh0;
        *(__nv_bfloat162*)(sAh + r*136 + c4 + 2) = hh1;
        __nv_bfloat162 ll0, ll1;
        ll0.x=__float2bfloat16(v.x-__bfloat162float(h0));
        ll0.y=__float2bfloat16(v.y-__bfloat162float(h1));
        ll1.x=__float2bfloat16(v.z-__bfloat162float(h2));
        ll1.y=__float2bfloat16(v.w-__bfloat162float(h3));
        *(__nv_bfloat162*)(sAl + r*136 + c4)     = ll0;
        *(__nv_bfloat162*)(sAl + r*136 + c4 + 2) = ll1;
    }

    const int w  = tid>>5;
    const int wr = w>>2;
    const int wc = w&3;

    for (int s = 0; s < nslots; s++) {
        const bf16* Wh = g_w_hi + (size_t)(slot0+s)*16384;
        const bf16* Wl = g_w_lo + (size_t)(slot0+s)*16384;
        for (int i = tid; i < 1024; i += 512) {
            int r = i>>3, c16 = (i&7)*16;
            *(uint4*)(sWh + r*136 + c16)     = *(const uint4*)(Wh + r*128 + c16);
            *(uint4*)(sWh + r*136 + c16 + 8) = *(const uint4*)(Wh + r*128 + c16 + 8);
            *(uint4*)(sWl + r*136 + c16)     = *(const uint4*)(Wl + r*128 + c16);
            *(uint4*)(sWl + r*136 + c16 + 8) = *(const uint4*)(Wl + r*128 + c16 + 8);
        }
        __syncthreads();

        wmma::fragment<wmma::accumulator,16,16,16,float> acc[2][2];
        #pragma unroll
        for (int i=0;i<2;i++)
            #pragma unroll
            for (int j=0;j<2;j++) wmma::fill_fragment(acc[i][j], 0.f);

        #pragma unroll
        for (int kk=0; kk<8; kk++) {
            wmma::fragment<wmma::matrix_a,16,16,16,bf16,wmma::row_major> ah[2], al[2];
            #pragma unroll
            for (int mt=0; mt<2; mt++) {
                wmma::load_matrix_sync(ah[mt], sAh + (wr*32+mt*16)*136 + kk*16, 136);
                wmma::load_matrix_sync(al[mt], sAl + (wr*32+mt*16)*136 + kk*16, 136);
            }
            #pragma unroll
            for (int nt=0; nt<2; nt++) {
                wmma::fragment<wmma::matrix_b,16,16,16,bf16,wmma::row_major> bh, bl;
                wmma::load_matrix_sync(bh, sWh + kk*16*136 + wc*32 + nt*16, 136);
                wmma::load_matrix_sync(bl, sWl + kk*16*136 + wc*32 + nt*16, 136);
                #pragma unroll
                for (int mt=0; mt<2; mt++) {
                    wmma::mma_sync(acc[mt][nt], ah[mt], bh, acc[mt][nt]);
                    wmma::mma_sync(acc[mt][nt], ah[mt], bl, acc[mt][nt]);
                    wmma::mma_sync(acc[mt][nt], al[mt], bh, acc[mt][nt]);
                }
            }
        }
        __syncthreads();
        #pragma unroll
        for (int mt=0; mt<2; mt++)
            #pragma unroll
            for (int nt=0; nt<2; nt++)
                wmma::store_matrix_sync(sC + (wr*32+mt*16)*132 + wc*32 + nt*16, acc[mt][nt], 132, wmma::mem_row_major);
        __syncthreads();

        float* C = (s == 0) ? O0 : ((s == 1) ? O1 : O2);
        for (int i = tid; i < 4096; i += 512) {
            int r = i>>5, c4 = (i&31)*4;
            if (m0 + r < M) {
                float4 v = *(const float4*)(sC + r*132 + c4);
                if (bias) { v.x += bias[c4]; v.y += bias[c4+1]; v.z += bias[c4+2]; v.w += bias[c4+3]; }
                *(float4*)(C + (size_t)(m0+r)*128 + c4) = v;
            }
        }
        __syncthreads();
    }
}

// ---------------- fused output: (aggv + z@Wev) @ (-Wout) + bout ----------------
// Phase A: Wev in smem; per-warp ykern loop computes aggv+y -> bf16 hi/lo straight into A tiles.
// Phase B: stage -Wout, wmma GEMM, bias epilogue.
__global__ __launch_bounds__(512) void gemm_out_fused(
    const float* __restrict__ Wev, float* __restrict__ out,
    const float* __restrict__ bias, int M)
{
    extern __shared__ char sm[];
    bf16* sAh = (bf16*)sm;
    bf16* sAl = sAh + 128*136;
    bf16* sWh = sAl + 128*136;
    bf16* sWl = sWh + 128*136;
    float* sC = (float*)(sm + 2*128*136*2);
    float* WV = (float*)(sm + 2*128*136*2);   // 65536 <= 69632, overlays sWh/sWl

    const int tid = threadIdx.x;
    const int m0  = blockIdx.x*128;
    const int w   = tid>>5;
    const int lane = tid&31;
    const int c4  = lane*4;
    const int h   = lane>>2;

    // Phase A: Wev -> smem
    for (int i = tid; i < 4096; i += 512)
        *(float4*)(WV + i*4) = *(const float4*)(Wev + i*4);
    __syncthreads();

    // y = z @ Wev + aggv, written as bf16 hi/lo into sAh/sAl (warp handles 8 nodes)
    #pragma unroll
    for (int g = 0; g < 2; g++) {
        const int nb = m0 + w*8 + g*4;
        const int jmax = (nb + 4 <= NN) ? 4 : (nb < NN ? NN - nb : 0);

        float4 acc[4];
        #pragma unroll
        for (int j = 0; j < 4; j++)
            acc[j] = (j < jmax) ? *(const float4*)(g_aggv + (size_t)(nb+j)*128 + c4)
                                : make_float4(0.f,0.f,0.f,0.f);

        const float* zr0 = g_z + (size_t)nb*1024 + h*128;
        for (int kb = 0; kb < 32; kb++) {
            float4 z4[4];
            #pragma unroll
            for (int j = 0; j < 4; j++)
                z4[j] = (j < jmax) ? *(const float4*)(zr0 + j*1024 + kb*4)
                                   : make_float4(0.f,0.f,0.f,0.f);
            #pragma unroll
            for (int kk = 0; kk < 4; kk++) {
                float4 w4 = *(const float4*)(WV + (kb*4 + kk)*128 + c4);
                #pragma unroll
                for (int j = 0; j < 4; j++) {
                    float zb = (kk==0) ? z4[j].x : (kk==1) ? z4[j].y : (kk==2) ? z4[j].z : z4[j].w;
                    acc[j].x += zb*w4.x; acc[j].y += zb*w4.y;
                    acc[j].z += zb*w4.z; acc[j].w += zb*w4.w;
                }
            }
        }
        #pragma unroll
        for (int j = 0; j < 4; j++) {
            const int row = w*8 + g*4 + j;
            float4 v = acc[j];
            bf16 h0=__float2bfloat16(v.x), h1=__float2bfloat16(v.y);
            bf16 h2=__float2bfloat16(v.z), h3=__float2bfloat16(v.w);
            __nv_bfloat162 hh0; hh0.x=h0; hh0.y=h1;
            __nv_bfloat162 hh1; hh1.x=h2; hh1.y=h3;
            *(__nv_bfloat162*)(sAh + row*136 + c4)     = hh0;
            *(__nv_bfloat162*)(sAh + row*136 + c4 + 2) = hh1;
            __nv_bfloat162 ll0, ll1;
            ll0.x=__float2bfloat16(v.x-__bfloat162float(h0));
            ll0.y=__float2bfloat16(v.y-__bfloat162float(h1));
            ll1.x=__float2bfloat16(v.z-__bfloat162float(h2));
            ll1.y=__float2bfloat16(v.w-__bfloat162float(h3));
            *(__nv_bfloat162*)(sAl + row*136 + c4)     = ll0;
            *(__nv_bfloat162*)(sAl + row*136 + c4 + 2) = ll1;
        }
    }
    __syncthreads();

    // Phase B: stage -Wout (slot 3), overwrites WV (y reads done)
    {
        const bf16* Wh = g_w_hi + 3*16384;
        const bf16* Wl = g_w_lo + 3*16384;
        for (int i = tid; i < 1024; i += 512) {
            int r = i>>3, c16 = (i&7)*16;
            *(uint4*)(sWh + r*136 + c16)     = *(const uint4*)(Wh + r*128 + c16);
            *(uint4*)(sWh + r*136 + c16 + 8) = *(const uint4*)(Wh + r*128 + c16 + 8);
            *(uint4*)(sWl + r*136 + c16)     = *(const uint4*)(Wl + r*128 + c16);
            *(uint4*)(sWl + r*136 + c16 + 8) = *(const uint4*)(Wl + r*128 + c16 + 8);
        }
    }
    __syncthreads();

    const int wr = w>>2;
    const int wc = w&3;
    wmma::fragment<wmma::accumulator,16,16,16,float> acc[2][2];
    #pragma unroll
    for (int i=0;i<2;i++)
        #pragma unroll
        for (int j=0;j<2;j++) wmma::fill_fragment(acc[i][j], 0.f);

    #pragma unroll
    for (int kk=0; kk<8; kk++) {
        wmma::fragment<wmma::matrix_a,16,16,16,bf16,wmma::row_major> ah[2], al[2];
        #pragma unroll
        for (int mt=0; mt<2; mt++) {
            wmma::load_matrix_sync(ah[mt], sAh + (wr*32+mt*16)*136 + kk*16, 136);
            wmma::load_matrix_sync(al[mt], sAl + (wr*32+mt*16)*136 + kk*16, 136);
        }
        #pragma unroll
        for (int nt=0; nt<2; nt++) {
            wmma::fragment<wmma::matrix_b,16,16,16,bf16,wmma::row_major> bh, bl;
            wmma::load_matrix_sync(bh, sWh + kk*16*136 + wc*32 + nt*16, 136);
            wmma::load_matrix_sync(bl, sWl + kk*16*136 + wc*32 + nt*16, 136);
            #pragma unroll
            for (int mt=0; mt<2; mt++) {
                wmma::mma_sync(acc[mt][nt], ah[mt], bh, acc[mt][nt]);
                wmma::mma_sync(acc[mt][nt], ah[mt], bl, acc[mt][nt]);
                wmma::mma_sync(acc[mt][nt], al[mt], bh, acc[mt][nt]);
            }
        }
    }
    __syncthreads();
    #pragma unroll
    for (int mt=0; mt<2; mt++)
        #pragma unroll
        for (int nt=0; nt<2; nt++)
            wmma::store_matrix_sync(sC + (wr*32+mt*16)*132 + wc*32 + nt*16, acc[mt][nt], 132, wmma::mem_row_major);
    __syncthreads();

    for (int i = tid; i < 4096; i += 512) {
        int r = i>>5, cc = (i&31)*4;
        if (m0 + r < M) {
            float4 v = *(const float4*)(sC + r*132 + cc);
            v.x += bias[cc]; v.y += bias[cc+1]; v.z += bias[cc+2]; v.w += bias[cc+3];
            *(float4*)(out + (size_t)(m0+r)*128 + cc) = v;
        }
    }
}

// ---------------- edge kernel v6: balanced QK across subs; 5 CTAs/SM ----------------
#define EO_E    0                      // 64*128*4 = 32768
#define EO_SE0  32768                  // 2048   (reused as aggv partial)
#define EO_SE1  34816                  // 2048
#define EO_SA   36864                  // 2048
#define EO_DST  38912                  // 256
#define EO_WEXP 39168                  // 256
#define EDGE_SMEM 39424

__global__ __launch_bounds__(256, 5) void edge_kernel(
    const float* __restrict__ edges, const int* __restrict__ eidx,
    const float* __restrict__ Wexp)
{
    extern __shared__ char sm[];
    float* Es    = (float*)(sm + EO_E);     // [64][128]
    float* SE0   = (float*)(sm + EO_SE0);
    float* SE1   = (float*)(sm + EO_SE1);
    float* SA    = (float*)(sm + EO_SA);
    int*   DSTs  = (int*)  (sm + EO_DST);
    float* WEXPs = (float*)(sm + EO_WEXP);

    const int tid  = threadIdx.x;
    const int w    = tid>>5;
    const int lane = tid&31;
    const int nl   = w>>1;
    const int sub  = w&1;
    const int t    = blockIdx.x;
    const int n0   = t*4;
    const int e0   = t*64;
    const int node = n0 + nl;

    for (int i = tid; i < 2048; i += 256) {
        int r = i>>5, c4 = (i&31)*4;
        *(float4*)(Es + r*128 + c4) = *(const float4*)(edges + (size_t)(e0+r)*128 + c4);
    }
    if (tid < 64) DSTs[tid] = eidx[NE + e0 + tid];
    if (tid >= 64 && tid < 128) WEXPs[tid-64] = Wexp[tid-64];

    const int h = lane>>2;
    const int q = lane&3;

    float4 Pr[4];
    #pragma unroll
    for (int i = 0; i < 4; i++)
        Pr[i] = *(const float4*)(g_P + ((size_t)node*8 + h)*128 + q*4 + (sub*4 + i)*16);
    float4 Qr = *(const float4*)(g_Q + (size_t)node*128 + lane*4);
    __syncthreads();

    float* SEo = sub ? SE1 : SE0;
    #pragma unroll
    for (int e = 0; e < 16; e++) {
        const int row = nl*16 + e;
        const float* er = Es + row*128;
        float s = 0.f;
        #pragma unroll
        for (int i = 0; i < 4; i++) {
            float4 E4 = *(const float4*)(er + q*4 + (sub*4 + i)*16);
            s += E4.x*Pr[i].x + E4.y*Pr[i].y + E4.z*Pr[i].z + E4.w*Pr[i].w;
        }
        if ((e>>3) == sub) {
            int dst = DSTs[row];
            float4 K4 = *(const float4*)(g_KS + (size_t)dst*128 + lane*4);
            s += Qr.x*K4.x + Qr.y*K4.y + Qr.z*K4.z + Qr.w*K4.w;
        }
        s += __shfl_xor_sync(0xffffffffu, s, 1);
        s += __shfl_xor_sync(0xffffffffu, s, 2);
        if (q == 0) SEo[row*8 + h] = s;
    }
    __syncthreads();

    for (int i = tid; i < 512; i += 256) {
        int e = i>>3, he = i&7;
        float v = 0.f;
        #pragma unroll
        for (int hh = 0; hh < 8; hh++)
            v += (SE0[e*8 + hh] + SE1[e*8 + hh])*WEXPs[hh*8 + he];
        SA[i] = v;
    }
    __syncthreads();

    if (tid < 32) {
        int nd = tid>>3, he = tid&7;
        int base = nd*16;
        float m = -1e30f;
        #pragma unroll
        for (int j = 0; j < 16; j++) m = fmaxf(m, SA[(base+j)*8 + he]);
        float ex[16], su = 0.f;
        #pragma unroll
        for (int j = 0; j < 16; j++) { ex[j] = __expf(SA[(base+j)*8 + he] - m); su += ex[j]; }
        float inv = 1.f/su;
        #pragma unroll
        for (int j = 0; j < 16; j++) SA[(base+j)*8 + he] = ex[j]*inv;
    }
    __syncthreads();

    const int c4 = lane*4;
    {
        const int hb = sub*4;
        float4 zac[4];
        #pragma unroll
        for (int j = 0; j < 4; j++) zac[j] = make_float4(0.f,0.f,0.f,0.f);
        #pragma unroll
        for (int e = 0; e < 16; e++) {
            const int row = nl*16 + e;
            float4 a4 = *(const float4*)(SA + row*8 + hb);
            float4 E4 = *(const float4*)(Es + row*128 + c4);
            zac[0].x += a4.x*E4.x; zac[0].y += a4.x*E4.y; zac[0].z += a4.x*E4.z; zac[0].w += a4.x*E4.w;
            zac[1].x += a4.y*E4.x; zac[1].y += a4.y*E4.y; zac[1].z += a4.y*E4.z; zac[1].w += a4.y*E4.w;
            zac[2].x += a4.z*E4.x; zac[2].y += a4.z*E4.y; zac[2].z += a4.z*E4.z; zac[2].w += a4.z*E4.w;
            zac[3].x += a4.w*E4.x; zac[3].y += a4.w*E4.y; zac[3].z += a4.w*E4.z; zac[3].w += a4.w*E4.w;
        }
        #pragma unroll
        for (int j = 0; j < 4; j++)
            *(float4*)(g_z + (size_t)node*1024 + (sub*4 + j)*128 + c4) = zac[j];
    }

    const int h2 = lane>>2;
    float4 vacc = make_float4(0.f,0.f,0.f,0.f);
    #pragma unroll
    for (int e = 0; e < 8; e++) {
        const int row = nl*16 + sub*8 + e;
        int dst = DSTs[row];
        float a = SA[row*8 + h2];
        float4 V4 = *(const float4*)(g_V + (size_t)dst*128 + c4);
        vacc.x += a*V4.x; vacc.y += a*V4.y; vacc.z += a*V4.z; vacc.w += a*V4.w;
    }
    float* PS = SE0;
    if (sub == 0) *(float4*)(PS + nl*128 + c4) = vacc;
    __syncthreads();
    if (sub == 1) {
        float4 p = *(const float4*)(PS + nl*128 + c4);
        vacc.x += p.x; vacc.y += p.y; vacc.z += p.z; vacc.w += p.w;
        *(float4*)(g_aggv + (size_t)node*128 + c4) = vacc;
    }
}

// ---------------- launch ----------------
extern "C" void kernel_launch(void* const* d_in, const int* in_sizes, int n_in,
                              void* d_out, int out_size)
{
    const float* x    = (const float*)d_in[0];
    const float* edges= (const float*)d_in[1];
    const int*   eidx = (const int*)  d_in[2];
    const float* Wq   = (const float*)d_in[3];
    const float* Wk   = (const float*)d_in[4];
    const float* Wv   = (const float*)d_in[5];
    const float* Wek  = (const float*)d_in[6];
    const float* Wev  = (const float*)d_in[7];
    const float* Wexp = (const float*)d_in[8];
    const float* Wout = (const float*)d_in[9];
    const float* bout = (const float*)d_in[10];
    float* out = (float*)d_out;

    float *Qg, *KSg, *Vg;
    cudaGetSymbolAddress((void**)&Qg,  g_Q);
    cudaGetSymbolAddress((void**)&KSg, g_KS);
    cudaGetSymbolAddress((void**)&Vg,  g_V);

    cudaFuncSetAttribute(gemm_multi,     cudaFuncAttributeMaxDynamicSharedMemorySize, GEMM_SMEM);
    cudaFuncSetAttribute(gemm_out_fused, cudaFuncAttributeMaxDynamicSharedMemorySize, GEMM_SMEM);
    cudaFuncSetAttribute(pkern,          cudaFuncAttributeMaxDynamicSharedMemorySize, PK_SMEM);
    cudaFuncSetAttribute(edge_kernel,    cudaFuncAttributeMaxDynamicSharedMemorySize, EDGE_SMEM);

    // weight prep (4 split slots + WekT transpose in slot 4)
    wsplit_kernel<<<dim3(64,5),256>>>(Wq, Wk, Wv, Wout, Wek);

    // Q / KS / V
    gemm_multi<<<(NN+127)/128,512,GEMM_SMEM>>>(x, 0, 3, Qg, KSg, Vg, nullptr, NN);

    // P[n,h,k]  (64 nodes x 4 heads per block; 4 CTAs/SM)
    pkern<<<dim3((NN+63)/64, 2),512,PK_SMEM>>>();

    // edge pass: scores -> expansion -> softmax -> z + aggv
    edge_kernel<<<NT4,256,EDGE_SMEM>>>(edges, eidx, Wexp);

    // out = (aggv + z@Wev) @ (-Wout) + bout  (ykern fused in)
    gemm_out_fused<<<(NN+127)/128,512,GEMM_SMEM>>>(Wev, out, bout, NN);
}

// round 16
// speedup vs baseline: 1.0904x; 1.0904x over previous
#include <cuda_runtime.h>
#include <cuda_bf16.h>
#include <cuda_fp16.h>
#include <mma.h>
#include <cstdint>

using namespace nvcuda;
typedef __nv_bfloat16 bf16;

#define NN   20000
#define DEGC 16
#define NE   (NN*DEGC)     // 320000
#define DIMC 128
#define SCALEC 0.25f       // HD^-0.5, HD=16
#define NT4  5000          // edge tiles of 4 nodes / 64 edges

// ---------------- scratch (__device__ globals; no allocation allowed) ----------------
__device__ float  g_Q   [NN*DIMC];
__device__ float  g_KS  [NN*DIMC];
__device__ float  g_V   [NN*DIMC];
__device__ __half g_P   [NN*8*DIMC];   // P[n][h][k] fp16 (ferry only)
__device__ __half g_z   [NN*8*DIMC];   // z[n][h][k] fp16 (ferry only)
__device__ float  g_aggv[NN*DIMC];     // sum_e a*V[dst]  (+ z@Wev added by ykern)
__device__ float  g_WekT[DIMC*DIMC];   // WekT[d][k] = Wek[k][d]*S
// weight slots hi/lo, row-major [k][n]: 0=Wq 1=Wk*S 2=Wv 3=-Wout
__device__ bf16   g_w_hi[4*DIMC*DIMC];
__device__ bf16   g_w_lo[4*DIMC*DIMC];

__device__ __forceinline__ uint2 pack_h4(float4 v) {
    __half2 a = __floats2half2_rn(v.x, v.y);
    __half2 b = __floats2half2_rn(v.z, v.w);
    uint2 r;
    r.x = *(uint32_t*)&a;
    r.y = *(uint32_t*)&b;
    return r;
}
__device__ __forceinline__ float4 unpack_h4(uint2 u) {
    __half2 a = *(__half2*)&u.x;
    __half2 b = *(__half2*)&u.y;
    float2 fa = __half22float2(a), fb = __half22float2(b);
    return make_float4(fa.x, fa.y, fb.x, fb.y);
}

// ---------------- weight split (4 slots) + WekT transpose (slot 4) ----------------
__global__ void wsplit_kernel(const float* __restrict__ w0, const float* __restrict__ w1,
                              const float* __restrict__ w2, const float* __restrict__ w3,
                              const float* __restrict__ Wek)
{
    int s = blockIdx.y;
    int i = blockIdx.x*256 + threadIdx.x;
    if (s == 4) {
        int d = i>>7, k = i&127;
        g_WekT[i] = Wek[k*128 + d] * SCALEC;
        return;
    }
    const float* srcs[4] = {w0, w1, w2, w3};
    const float  scl [4] = {1.f, SCALEC, 1.f, -1.f};
    float v = srcs[s][i] * scl[s];
    bf16 h = __float2bfloat16(v);
    g_w_hi[s*16384 + i] = h;
    g_w_lo[s*16384 + i] = __float2bfloat16(v - __bfloat162float(h));
}

// ---------------- P precompute v2: block = 64 nodes x 4 heads; 4 CTAs/SM ----------------
#define PK_SMEM (64*128*4 + 64*64*4)
__global__ __launch_bounds__(512) void pkern()
{
    extern __shared__ float smf[];
    float* WT = smf;                 // [dlocal 0..63][k 0..127]
    float* Qs = smf + 8192;          // [node 0..63][dlocal 0..63]

    const int tid = threadIdx.x;
    const int nb0 = blockIdx.x*64;
    const int h0  = blockIdx.y*4;

    for (int i = tid; i < 2048; i += 512)
        *(float4*)(WT + i*4) = *(const float4*)(g_WekT + (size_t)h0*16*128 + i*4);
    for (int i = tid; i < 1024; i += 512) {
        int r = i>>4, c4 = (i&15)*4;
        int n = nb0 + r;
        float4 v = make_float4(0.f,0.f,0.f,0.f);
        if (n < NN) v = *(const float4*)(g_Q + (size_t)n*128 + h0*16 + c4);
        *(float4*)(Qs + r*64 + c4) = v;
    }
    __syncthreads();

    const int w = tid>>5, lane = tid&31;
    const int nl0 = w*4;
    const int k4  = lane*4;

    #pragma unroll
    for (int h = 0; h < 4; h++) {
        float4 acc[4];
        #pragma unroll
        for (int j = 0; j < 4; j++) acc[j] = make_float4(0.f,0.f,0.f,0.f);
        #pragma unroll
        for (int dq = 0; dq < 4; dq++) {
            float4 q4[4];
            #pragma unroll
            for (int j = 0; j < 4; j++)
                q4[j] = *(const float4*)(Qs + (nl0 + j)*64 + h*16 + dq*4);
            #pragma unroll
            for (int dd = 0; dd < 4; dd++) {
                float4 w4 = *(const float4*)(WT + (h*16 + dq*4 + dd)*128 + k4);
                #pragma unroll
                for (int j = 0; j < 4; j++) {
                    float qv = (dd==0) ? q4[j].x : (dd==1) ? q4[j].y : (dd==2) ? q4[j].z : q4[j].w;
                    acc[j].x += qv*w4.x; acc[j].y += qv*w4.y;
                    acc[j].z += qv*w4.z; acc[j].w += qv*w4.w;
                }
            }
        }
        #pragma unroll
        for (int j = 0; j < 4; j++) {
            int n = nb0 + nl0 + j;
            if (n < NN)
                *(uint2*)(g_P + ((size_t)n*8 + h0 + h)*128 + k4) = pack_h4(acc[j]);
        }
    }
}

// ---------------- y: aggv += z @ Wev (block-diagonal); block = 64 nodes ----------------
#define YK_SMEM (128*128*4)   // Wev 64KB
__global__ __launch_bounds__(512) void ykern(const float* __restrict__ Wev)
{
    extern __shared__ float WV[];    // [k][c] natural
    const int tid = threadIdx.x;
    for (int i = tid; i < 4096; i += 512)
        *(float4*)(WV + i*4) = *(const float4*)(Wev + i*4);
    __syncthreads();

    const int w = tid>>5, lane = tid&31;
    const int nb = blockIdx.x*64 + w*4;
    const int c4 = lane*4;
    const int h  = lane>>2;

    float4 acc[4];
    #pragma unroll
    for (int j = 0; j < 4; j++) acc[j] = make_float4(0.f,0.f,0.f,0.f);

    const int jmax = (nb + 4 <= NN) ? 4 : (nb < NN ? NN - nb : 0);
    const __half* zr0 = g_z + (size_t)nb*1024 + h*128;

    for (int kb = 0; kb < 32; kb++) {
        float4 z4[4];
        #pragma unroll
        for (int j = 0; j < 4; j++)
            z4[j] = (j < jmax) ? unpack_h4(*(const uint2*)(zr0 + j*1024 + kb*4))
                               : make_float4(0.f,0.f,0.f,0.f);
        #pragma unroll
        for (int kk = 0; kk < 4; kk++) {
            float4 w4 = *(const float4*)(WV + (kb*4 + kk)*128 + c4);
            #pragma unroll
            for (int j = 0; j < 4; j++) {
                float zb = (kk==0) ? z4[j].x : (kk==1) ? z4[j].y : (kk==2) ? z4[j].z : z4[j].w;
                acc[j].x += zb*w4.x; acc[j].y += zb*w4.y;
                acc[j].z += zb*w4.z; acc[j].w += zb*w4.w;
            }
        }
    }
    #pragma unroll
    for (int j = 0; j < 4; j++) {
        if (j < jmax) {
            float* ar = g_aggv + (size_t)(nb + j)*128 + c4;
            float4 av = *(const float4*)ar;
            av.x += acc[j].x; av.y += acc[j].y; av.z += acc[j].z; av.w += acc[j].w;
            *(float4*)ar = av;
        }
    }
}

// ---------------- multi-slot [M,128]@[128,128] split-bf16 GEMM ----------------
#define GEMM_SMEM (4*128*136*2)
__global__ __launch_bounds__(512) void gemm_multi(
    const float* __restrict__ A, int slot0, int nslots,
    float* __restrict__ O0, float* __restrict__ O1, float* __restrict__ O2,
    const float* __restrict__ bias, int M)
{
    extern __shared__ char sm[];
    bf16* sAh = (bf16*)sm;
    bf16* sAl = sAh + 128*136;
    bf16* sWh = sAl + 128*136;
    bf16* sWl = sWh + 128*136;
    float* sC = (float*)(sm + 2*128*136*2);

    const int tid = threadIdx.x;
    const int m0  = blockIdx.x*128;

    for (int i = tid; i < 4096; i += 512) {
        int r = i>>5, c4 = (i&31)*4;
        float4 v = make_float4(0.f,0.f,0.f,0.f);
        if (m0 + r < M) v = *(const float4*)(A + (size_t)(m0+r)*128 + c4);
        bf16 h0=__float2bfloat16(v.x), h1=__float2bfloat16(v.y);
        bf16 h2=__float2bfloat16(v.z), h3=__float2bfloat16(v.w);
        __nv_bfloat162 hh0; hh0.x=h0; hh0.y=h1;
        __nv_bfloat162 hh1; hh1.x=h2; hh1.y=h3;
        *(__nv_bfloat162*)(sAh + r*136 + c4)     = hh0;
        *(__nv_bfloat162*)(sAh + r*136 + c4 + 2) = hh1;
        __nv_bfloat162 ll0, ll1;
        ll0.x=__float2bfloat16(v.x-__bfloat162float(h0));
        ll0.y=__float2bfloat16(v.y-__bfloat162float(h1));
        ll1.x=__float2bfloat16(v.z-__bfloat162float(h2));
        ll1.y=__float2bfloat16(v.w-__bfloat162float(h3));
        *(__nv_bfloat162*)(sAl + r*136 + c4)     = ll0;
        *(__nv_bfloat162*)(sAl + r*136 + c4 + 2) = ll1;
    }

    const int w  = tid>>5;
    const int wr = w>>2;
    const int wc = w&3;

    for (int s = 0; s < nslots; s++) {
        const bf16* Wh = g_w_hi + (size_t)(slot0+s)*16384;
        const bf16* Wl = g_w_lo + (size_t)(slot0+s)*16384;
        for (int i = tid; i < 1024; i += 512) {
            int r = i>>3, c16 = (i&7)*16;
            *(uint4*)(sWh + r*136 + c16)     = *(const uint4*)(Wh + r*128 + c16);
            *(uint4*)(sWh + r*136 + c16 + 8) = *(const uint4*)(Wh + r*128 + c16 + 8);
            *(uint4*)(sWl + r*136 + c16)     = *(const uint4*)(Wl + r*128 + c16);
            *(uint4*)(sWl + r*136 + c16 + 8) = *(const uint4*)(Wl + r*128 + c16 + 8);
        }
        __syncthreads();

        wmma::fragment<wmma::accumulator,16,16,16,float> acc[2][2];
        #pragma unroll
        for (int i=0;i<2;i++)
            #pragma unroll
            for (int j=0;j<2;j++) wmma::fill_fragment(acc[i][j], 0.f);

        #pragma unroll
        for (int kk=0; kk<8; kk++) {
            wmma::fragment<wmma::matrix_a,16,16,16,bf16,wmma::row_major> ah[2], al[2];
            #pragma unroll
            for (int mt=0; mt<2; mt++) {
                wmma::load_matrix_sync(ah[mt], sAh + (wr*32+mt*16)*136 + kk*16, 136);
                wmma::load_matrix_sync(al[mt], sAl + (wr*32+mt*16)*136 + kk*16, 136);
            }
            #pragma unroll
            for (int nt=0; nt<2; nt++) {
                wmma::fragment<wmma::matrix_b,16,16,16,bf16,wmma::row_major> bh, bl;
                wmma::load_matrix_sync(bh, sWh + kk*16*136 + wc*32 + nt*16, 136);
                wmma::load_matrix_sync(bl, sWl + kk*16*136 + wc*32 + nt*16, 136);
                #pragma unroll
                for (int mt=0; mt<2; mt++) {
                    wmma::mma_sync(acc[mt][nt], ah[mt], bh, acc[mt][nt]);
                    wmma::mma_sync(acc[mt][nt], ah[mt], bl, acc[mt][nt]);
                    wmma::mma_sync(acc[mt][nt], al[mt], bh, acc[mt][nt]);
                }
            }
        }
        __syncthreads();
        #pragma unroll
        for (int mt=0; mt<2; mt++)
            #pragma unroll
            for (int nt=0; nt<2; nt++)
                wmma::store_matrix_sync(sC + (wr*32+mt*16)*132 + wc*32 + nt*16, acc[mt][nt], 132, wmma::mem_row_major);
        __syncthreads();

        float* C = (s == 0) ? O0 : ((s == 1) ? O1 : O2);
        for (int i = tid; i < 4096; i += 512) {
            int r = i>>5, c4 = (i&31)*4;
            if (m0 + r < M) {
                float4 v = *(const float4*)(sC + r*132 + c4);
                if (bias) { v.x += bias[c4]; v.y += bias[c4+1]; v.z += bias[c4+2]; v.w += bias[c4+3]; }
                *(float4*)(C + (size_t)(m0+r)*128 + c4) = v;
            }
        }
        __syncthreads();
    }
}

// ---------------- edge kernel v6 (R14 best) + fp16 P/z ----------------
#define EO_E    0                      // 64*128*4 = 32768
#define EO_SE0  32768                  // 2048   (reused as aggv partial)
#define EO_SE1  34816                  // 2048
#define EO_SA   36864                  // 2048
#define EO_DST  38912                  // 256
#define EO_WEXP 39168                  // 256
#define EDGE_SMEM 39424

__global__ __launch_bounds__(256, 5) void edge_kernel(
    const float* __restrict__ edges, const int* __restrict__ eidx,
    const float* __restrict__ Wexp)
{
    extern __shared__ char sm[];
    float* Es    = (float*)(sm + EO_E);     // [64][128]
    float* SE0   = (float*)(sm + EO_SE0);
    float* SE1   = (float*)(sm + EO_SE1);
    float* SA    = (float*)(sm + EO_SA);
    int*   DSTs  = (int*)  (sm + EO_DST);
    float* WEXPs = (float*)(sm + EO_WEXP);

    const int tid  = threadIdx.x;
    const int w    = tid>>5;
    const int lane = tid&31;
    const int nl   = w>>1;         // local node 0..3
    const int sub  = w&1;          // k-half / QK-edge-half
    const int t    = blockIdx.x;
    const int n0   = t*4;
    const int e0   = t*64;
    const int node = n0 + nl;

    // ---- stage: E tile, dst, Wexp ----
    for (int i = tid; i < 2048; i += 256) {
        int r = i>>5, c4 = (i&31)*4;
        *(float4*)(Es + r*128 + c4) = *(const float4*)(edges + (size_t)(e0+r)*128 + c4);
    }
    if (tid < 64) DSTs[tid] = eidx[NE + e0 + tid];
    if (tid >= 64 && tid < 128) WEXPs[tid-64] = Wexp[tid-64];

    const int h = lane>>2;           // head owned by this lane
    const int q = lane&3;            // quad index

    // ---- P quarter-slice (fp16 -> fp32 regs); Q quad ----
    float4 Pr[4];
    #pragma unroll
    for (int i = 0; i < 4; i++)
        Pr[i] = unpack_h4(*(const uint2*)(g_P + ((size_t)node*8 + h)*128 + q*4 + (sub*4 + i)*16));
    float4 Qr = *(const float4*)(g_Q + (size_t)node*128 + lane*4);
    __syncthreads();

    // ---- scores: partial over sub's k-half; QK(dst) by edge-half owner ----
    float* SEo = sub ? SE1 : SE0;
    #pragma unroll
    for (int e = 0; e < 16; e++) {
        const int row = nl*16 + e;
        const float* er = Es + row*128;
        float s = 0.f;
        #pragma unroll
        for (int i = 0; i < 4; i++) {
            float4 E4 = *(const float4*)(er + q*4 + (sub*4 + i)*16);
            s += E4.x*Pr[i].x + E4.y*Pr[i].y + E4.z*Pr[i].z + E4.w*Pr[i].w;
        }
        if ((e>>3) == sub) {
            int dst = DSTs[row];
            float4 K4 = *(const float4*)(g_KS + (size_t)dst*128 + lane*4);
            s += Qr.x*K4.x + Qr.y*K4.y + Qr.z*K4.z + Qr.w*K4.w;
        }
        s += __shfl_xor_sync(0xffffffffu, s, 1);
        s += __shfl_xor_sync(0xffffffffu, s, 2);
        if (q == 0) SEo[row*8 + h] = s;
    }
    __syncthreads();

    // ---- head expansion SA = (SE0+SE1) @ Wexp ----
    for (int i = tid; i < 512; i += 256) {
        int e = i>>3, he = i&7;
        float v = 0.f;
        #pragma unroll
        for (int hh = 0; hh < 8; hh++)
            v += (SE0[e*8 + hh] + SE1[e*8 + hh])*WEXPs[hh*8 + he];
        SA[i] = v;
    }
    __syncthreads();

    // ---- segment softmax per (node, he) ----
    if (tid < 32) {
        int nd = tid>>3, he = tid&7;
        int base = nd*16;
        float m = -1e30f;
        #pragma unroll
        for (int j = 0; j < 16; j++) m = fmaxf(m, SA[(base+j)*8 + he]);
        float ex[16], su = 0.f;
        #pragma unroll
        for (int j = 0; j < 16; j++) { ex[j] = __expf(SA[(base+j)*8 + he] - m); su += ex[j]; }
        float inv = 1.f/su;
        #pragma unroll
        for (int j = 0; j < 16; j++) SA[(base+j)*8 + he] = ex[j]*inv;
    }
    __syncthreads();

    const int c4 = lane*4;           // lane's 4 consecutive cols / k
    // ---- z for this sub's 4 heads, all 16 edges (fp16 store) ----
    {
        const int hb = sub*4;
        float4 zac[4];
        #pragma unroll
        for (int j = 0; j < 4; j++) zac[j] = make_float4(0.f,0.f,0.f,0.f);
        #pragma unroll
        for (int e = 0; e < 16; e++) {
            const int row = nl*16 + e;
            float4 a4 = *(const float4*)(SA + row*8 + hb);   // broadcast
            float4 E4 = *(const float4*)(Es + row*128 + c4); // conflict-free
            zac[0].x += a4.x*E4.x; zac[0].y += a4.x*E4.y; zac[0].z += a4.x*E4.z; zac[0].w += a4.x*E4.w;
            zac[1].x += a4.y*E4.x; zac[1].y += a4.y*E4.y; zac[1].z += a4.y*E4.z; zac[1].w += a4.y*E4.w;
            zac[2].x += a4.z*E4.x; zac[2].y += a4.z*E4.y; zac[2].z += a4.z*E4.z; zac[2].w += a4.z*E4.w;
            zac[3].x += a4.w*E4.x; zac[3].y += a4.w*E4.y; zac[3].z += a4.w*E4.z; zac[3].w += a4.w*E4.w;
        }
        #pragma unroll
        for (int j = 0; j < 4; j++)
            *(uint2*)(g_z + (size_t)node*1024 + (hb + j)*128 + c4) = pack_h4(zac[j]);
    }

    // ---- aggv: this sub's 8 edges, all cols (V via LDG, L2-hot); combine via SE0 ----
    const int h2 = lane>>2;
    float4 vacc = make_float4(0.f,0.f,0.f,0.f);
    #pragma unroll
    for (int e = 0; e < 8; e++) {
        const int row = nl*16 + sub*8 + e;
        int dst = DSTs[row];
        float a = SA[row*8 + h2];
        float4 V4 = *(const float4*)(g_V + (size_t)dst*128 + c4);
        vacc.x += a*V4.x; vacc.y += a*V4.y; vacc.z += a*V4.z; vacc.w += a*V4.w;
    }
    float* PS = SE0;   // dead after expansion
    if (sub == 0) *(float4*)(PS + nl*128 + c4) = vacc;
    __syncthreads();
    if (sub == 1) {
        float4 p = *(const float4*)(PS + nl*128 + c4);
        vacc.x += p.x; vacc.y += p.y; vacc.z += p.z; vacc.w += p.w;
        *(float4*)(g_aggv + (size_t)node*128 + c4) = vacc;
    }
}

// ---------------- launch ----------------
extern "C" void kernel_launch(void* const* d_in, const int* in_sizes, int n_in,
                              void* d_out, int out_size)
{
    const float* x    = (const float*)d_in[0];
    const float* edges= (const float*)d_in[1];
    const int*   eidx = (const int*)  d_in[2];
    const float* Wq   = (const float*)d_in[3];
    const float* Wk   = (const float*)d_in[4];
    const float* Wv   = (const float*)d_in[5];
    const float* Wek  = (const float*)d_in[6];
    const float* Wev  = (const float*)d_in[7];
    const float* Wexp = (const float*)d_in[8];
    const float* Wout = (const float*)d_in[9];
    const float* bout = (const float*)d_in[10];
    float* out = (float*)d_out;

    float *Qg, *KSg, *Vg, *aggvg;
    cudaGetSymbolAddress((void**)&Qg,    g_Q);
    cudaGetSymbolAddress((void**)&KSg,   g_KS);
    cudaGetSymbolAddress((void**)&Vg,    g_V);
    cudaGetSymbolAddress((void**)&aggvg, g_aggv);

    cudaFuncSetAttribute(gemm_multi,  cudaFuncAttributeMaxDynamicSharedMemorySize, GEMM_SMEM);
    cudaFuncSetAttribute(pkern,       cudaFuncAttributeMaxDynamicSharedMemorySize, PK_SMEM);
    cudaFuncSetAttribute(ykern,       cudaFuncAttributeMaxDynamicSharedMemorySize, YK_SMEM);
    cudaFuncSetAttribute(edge_kernel, cudaFuncAttributeMaxDynamicSharedMemorySize, EDGE_SMEM);

    // weight prep (4 split slots + WekT transpose in slot 4)
    wsplit_kernel<<<dim3(64,5),256>>>(Wq, Wk, Wv, Wout, Wek);

    // Q / KS / V
    gemm_multi<<<(NN+127)/128,512,GEMM_SMEM>>>(x, 0, 3, Qg, KSg, Vg, nullptr, NN);

    // P[n,h,k]  (64 nodes x 4 heads per block; 4 CTAs/SM)
    pkern<<<dim3((NN+63)/64, 2),512,PK_SMEM>>>();

    // edge pass: scores -> expansion -> softmax -> z + aggv
    edge_kernel<<<NT4,256,EDGE_SMEM>>>(edges, eidx, Wexp);

    // aggv += z @ Wev (block-diagonal)
    ykern<<<(NN+63)/64,512,YK_SMEM>>>(Wev);

    // out = (aggv + y) @ (-Wout) + bout
    gemm_multi<<<(NN+127)/128,512,GEMM_SMEM>>>(aggvg, 3, 1, out, out, out, bout, NN);
}

// round 17
// speedup vs baseline: 1.2116x; 1.1112x over previous
#include <cuda_runtime.h>
#include <cuda_bf16.h>
#include <cuda_fp16.h>
#include <mma.h>
#include <cstdint>

using namespace nvcuda;
typedef __nv_bfloat16 bf16;

#define NN   20000
#define DEGC 16
#define NE   (NN*DEGC)     // 320000
#define DIMC 128
#define SCALEC 0.25f       // HD^-0.5, HD=16
#define NT4  5000          // edge tiles of 4 nodes / 64 edges

// ---------------- scratch (__device__ globals; no allocation allowed) ----------------
__device__ float  g_Q   [NN*DIMC];
__device__ float  g_KS  [NN*DIMC];
__device__ float  g_V   [NN*DIMC];
__device__ __half g_P   [NN*8*DIMC];   // P[n][h][k] fp16 (ferry only)
__device__ __half g_z   [NN*8*DIMC];   // z[n][h][k] fp16 (ferry only)
__device__ float  g_aggv[NN*DIMC];     // sum_e a*V[dst]  (+ z@Wev added by ykern)
__device__ float  g_WekT[DIMC*DIMC];   // WekT[d][k] = Wek[k][d]*S
// weight slots hi/lo, row-major [k][n]: 0=Wq 1=Wk*S 2=Wv 3=-Wout
__device__ bf16   g_w_hi[4*DIMC*DIMC];
__device__ bf16   g_w_lo[4*DIMC*DIMC];

__device__ __forceinline__ uint2 pack_h4(float4 v) {
    __half2 a = __floats2half2_rn(v.x, v.y);
    __half2 b = __floats2half2_rn(v.z, v.w);
    uint2 r;
    r.x = *(uint32_t*)&a;
    r.y = *(uint32_t*)&b;
    return r;
}
__device__ __forceinline__ float4 unpack_h4(uint2 u) {
    __half2 a = *(__half2*)&u.x;
    __half2 b = *(__half2*)&u.y;
    float2 fa = __half22float2(a), fb = __half22float2(b);
    return make_float4(fa.x, fa.y, fb.x, fb.y);
}

// ---------------- weight split (4 slots) + WekT transpose (slot 4) ----------------
__global__ void wsplit_kernel(const float* __restrict__ w0, const float* __restrict__ w1,
                              const float* __restrict__ w2, const float* __restrict__ w3,
                              const float* __restrict__ Wek)
{
    int s = blockIdx.y;
    int i = blockIdx.x*256 + threadIdx.x;
    if (s == 4) {
        int d = i>>7, k = i&127;
        g_WekT[i] = Wek[k*128 + d] * SCALEC;
        return;
    }
    const float* srcs[4] = {w0, w1, w2, w3};
    const float  scl [4] = {1.f, SCALEC, 1.f, -1.f};
    float v = srcs[s][i] * scl[s];
    bf16 h = __float2bfloat16(v);
    g_w_hi[s*16384 + i] = h;
    g_w_lo[s*16384 + i] = __float2bfloat16(v - __bfloat162float(h));
}

// ---------------- P precompute v2: block = 64 nodes x 4 heads; 4 CTAs/SM ----------------
#define PK_SMEM (64*128*4 + 64*64*4)
__global__ __launch_bounds__(512) void pkern()
{
    extern __shared__ float smf[];
    float* WT = smf;                 // [dlocal 0..63][k 0..127]
    float* Qs = smf + 8192;          // [node 0..63][dlocal 0..63]

    const int tid = threadIdx.x;
    const int nb0 = blockIdx.x*64;
    const int h0  = blockIdx.y*4;

    for (int i = tid; i < 2048; i += 512)
        *(float4*)(WT + i*4) = *(const float4*)(g_WekT + (size_t)h0*16*128 + i*4);
    for (int i = tid; i < 1024; i += 512) {
        int r = i>>4, c4 = (i&15)*4;
        int n = nb0 + r;
        float4 v = make_float4(0.f,0.f,0.f,0.f);
        if (n < NN) v = *(const float4*)(g_Q + (size_t)n*128 + h0*16 + c4);
        *(float4*)(Qs + r*64 + c4) = v;
    }
    __syncthreads();

    const int w = tid>>5, lane = tid&31;
    const int nl0 = w*4;
    const int k4  = lane*4;

    #pragma unroll
    for (int h = 0; h < 4; h++) {
        float4 acc[4];
        #pragma unroll
        for (int j = 0; j < 4; j++) acc[j] = make_float4(0.f,0.f,0.f,0.f);
        #pragma unroll
        for (int dq = 0; dq < 4; dq++) {
            float4 q4[4];
            #pragma unroll
            for (int j = 0; j < 4; j++)
                q4[j] = *(const float4*)(Qs + (nl0 + j)*64 + h*16 + dq*4);
            #pragma unroll
            for (int dd = 0; dd < 4; dd++) {
                float4 w4 = *(const float4*)(WT + (h*16 + dq*4 + dd)*128 + k4);
                #pragma unroll
                for (int j = 0; j < 4; j++) {
                    float qv = (dd==0) ? q4[j].x : (dd==1) ? q4[j].y : (dd==2) ? q4[j].z : q4[j].w;
                    acc[j].x += qv*w4.x; acc[j].y += qv*w4.y;
                    acc[j].z += qv*w4.z; acc[j].w += qv*w4.w;
                }
            }
        }
        #pragma unroll
        for (int j = 0; j < 4; j++) {
            int n = nb0 + nl0 + j;
            if (n < NN)
                *(uint2*)(g_P + ((size_t)n*8 + h0 + h)*128 + k4) = pack_h4(acc[j]);
        }
    }
}

// ---------------- y: aggv += z @ Wev (block-diagonal); block = 64 nodes ----------------
#define YK_SMEM (128*128*4)   // Wev 64KB
__global__ __launch_bounds__(512) void ykern(const float* __restrict__ Wev)
{
    extern __shared__ float WV[];    // [k][c] natural
    const int tid = threadIdx.x;
    for (int i = tid; i < 4096; i += 512)
        *(float4*)(WV + i*4) = *(const float4*)(Wev + i*4);
    __syncthreads();

    const int w = tid>>5, lane = tid&31;
    const int nb = blockIdx.x*64 + w*4;
    const int c4 = lane*4;
    const int h  = lane>>2;

    float4 acc[4];
    #pragma unroll
    for (int j = 0; j < 4; j++) acc[j] = make_float4(0.f,0.f,0.f,0.f);

    const int jmax = (nb + 4 <= NN) ? 4 : (nb < NN ? NN - nb : 0);
    const __half* zr0 = g_z + (size_t)nb*1024 + h*128;

    for (int kb = 0; kb < 32; kb++) {
        float4 z4[4];
        #pragma unroll
        for (int j = 0; j < 4; j++)
            z4[j] = (j < jmax) ? unpack_h4(*(const uint2*)(zr0 + j*1024 + kb*4))
                               : make_float4(0.f,0.f,0.f,0.f);
        #pragma unroll
        for (int kk = 0; kk < 4; kk++) {
            float4 w4 = *(const float4*)(WV + (kb*4 + kk)*128 + c4);
            #pragma unroll
            for (int j = 0; j < 4; j++) {
                float zb = (kk==0) ? z4[j].x : (kk==1) ? z4[j].y : (kk==2) ? z4[j].z : z4[j].w;
                acc[j].x += zb*w4.x; acc[j].y += zb*w4.y;
                acc[j].z += zb*w4.z; acc[j].w += zb*w4.w;
            }
        }
    }
    #pragma unroll
    for (int j = 0; j < 4; j++) {
        if (j < jmax) {
            float* ar = g_aggv + (size_t)(nb + j)*128 + c4;
            float4 av = *(const float4*)ar;
            av.x += acc[j].x; av.y += acc[j].y; av.z += acc[j].z; av.w += acc[j].w;
            *(float4*)ar = av;
        }
    }
}

// ---------------- multi-slot [M,128]@[128,128] split-bf16 GEMM ----------------
#define GEMM_SMEM (4*128*136*2)
__global__ __launch_bounds__(512) void gemm_multi(
    const float* __restrict__ A, int slot0, int nslots,
    float* __restrict__ O0, float* __restrict__ O1, float* __restrict__ O2,
    const float* __restrict__ bias, int M)
{
    extern __shared__ char sm[];
    bf16* sAh = (bf16*)sm;
    bf16* sAl = sAh + 128*136;
    bf16* sWh = sAl + 128*136;
    bf16* sWl = sWh + 128*136;
    float* sC = (float*)(sm + 2*128*136*2);

    const int tid = threadIdx.x;
    const int m0  = blockIdx.x*128;

    for (int i = tid; i < 4096; i += 512) {
        int r = i>>5, c4 = (i&31)*4;
        float4 v = make_float4(0.f,0.f,0.f,0.f);
        if (m0 + r < M) v = *(const float4*)(A + (size_t)(m0+r)*128 + c4);
        bf16 h0=__float2bfloat16(v.x), h1=__float2bfloat16(v.y);
        bf16 h2=__float2bfloat16(v.z), h3=__float2bfloat16(v.w);
        __nv_bfloat162 hh0; hh0.x=h0; hh0.y=h1;
        __nv_bfloat162 hh1; hh1.x=h2; hh1.y=h3;
        *(__nv_bfloat162*)(sAh + r*136 + c4)     = hh0;
        *(__nv_bfloat162*)(sAh + r*136 + c4 + 2) = hh1;
        __nv_bfloat162 ll0, ll1;
        ll0.x=__float2bfloat16(v.x-__bfloat162float(h0));
        ll0.y=__float2bfloat16(v.y-__bfloat162float(h1));
        ll1.x=__float2bfloat16(v.z-__bfloat162float(h2));
        ll1.y=__float2bfloat16(v.w-__bfloat162float(h3));
        *(__nv_bfloat162*)(sAl + r*136 + c4)     = ll0;
        *(__nv_bfloat162*)(sAl + r*136 + c4 + 2) = ll1;
    }

    const int w  = tid>>5;
    const int wr = w>>2;
    const int wc = w&3;

    for (int s = 0; s < nslots; s++) {
        const bf16* Wh = g_w_hi + (size_t)(slot0+s)*16384;
        const bf16* Wl = g_w_lo + (size_t)(slot0+s)*16384;
        for (int i = tid; i < 1024; i += 512) {
            int r = i>>3, c16 = (i&7)*16;
            *(uint4*)(sWh + r*136 + c16)     = *(const uint4*)(Wh + r*128 + c16);
            *(uint4*)(sWh + r*136 + c16 + 8) = *(const uint4*)(Wh + r*128 + c16 + 8);
            *(uint4*)(sWl + r*136 + c16)     = *(const uint4*)(Wl + r*128 + c16);
            *(uint4*)(sWl + r*136 + c16 + 8) = *(const uint4*)(Wl + r*128 + c16 + 8);
        }
        __syncthreads();

        wmma::fragment<wmma::accumulator,16,16,16,float> acc[2][2];
        #pragma unroll
        for (int i=0;i<2;i++)
            #pragma unroll
            for (int j=0;j<2;j++) wmma::fill_fragment(acc[i][j], 0.f);

        #pragma unroll
        for (int kk=0; kk<8; kk++) {
            wmma::fragment<wmma::matrix_a,16,16,16,bf16,wmma::row_major> ah[2], al[2];
            #pragma unroll
            for (int mt=0; mt<2; mt++) {
                wmma::load_matrix_sync(ah[mt], sAh + (wr*32+mt*16)*136 + kk*16, 136);
                wmma::load_matrix_sync(al[mt], sAl + (wr*32+mt*16)*136 + kk*16, 136);
            }
            #pragma unroll
            for (int nt=0; nt<2; nt++) {
                wmma::fragment<wmma::matrix_b,16,16,16,bf16,wmma::row_major> bh, bl;
                wmma::load_matrix_sync(bh, sWh + kk*16*136 + wc*32 + nt*16, 136);
                wmma::load_matrix_sync(bl, sWl + kk*16*136 + wc*32 + nt*16, 136);
                #pragma unroll
                for (int mt=0; mt<2; mt++) {
                    wmma::mma_sync(acc[mt][nt], ah[mt], bh, acc[mt][nt]);
                    wmma::mma_sync(acc[mt][nt], ah[mt], bl, acc[mt][nt]);
                    wmma::mma_sync(acc[mt][nt], al[mt], bh, acc[mt][nt]);
                }
            }
        }
        __syncthreads();
        #pragma unroll
        for (int mt=0; mt<2; mt++)
            #pragma unroll
            for (int nt=0; nt<2; nt++)
                wmma::store_matrix_sync(sC + (wr*32+mt*16)*132 + wc*32 + nt*16, acc[mt][nt], 132, wmma::mem_row_major);
        __syncthreads();

        float* C = (s == 0) ? O0 : ((s == 1) ? O1 : O2);
        for (int i = tid; i < 4096; i += 512) {
            int r = i>>5, c4 = (i&31)*4;
            if (m0 + r < M) {
                float4 v = *(const float4*)(sC + r*132 + c4);
                if (bias) { v.x += bias[c4]; v.y += bias[c4+1]; v.z += bias[c4+2]; v.w += bias[c4+3]; }
                *(float4*)(C + (size_t)(m0+r)*128 + c4) = v;
            }
        }
        __syncthreads();
    }
}

// ---------------- edge kernel v7: fp16 E staging; 5 CTAs/SM ----------------
#define EO_E    0                      // 64*128*2 = 16384  (fp16)
#define EO_SE0  16384                  // 2048   (reused as aggv partial)
#define EO_SE1  18432                  // 2048
#define EO_SA   20480                  // 2048
#define EO_DST  22528                  // 256
#define EO_WEXP 22784                  // 256
#define EDGE_SMEM 23040

__global__ __launch_bounds__(256, 5) void edge_kernel(
    const float* __restrict__ edges, const int* __restrict__ eidx,
    const float* __restrict__ Wexp)
{
    extern __shared__ char sm[];
    __half* Es   = (__half*)(sm + EO_E);    // [64][128] fp16
    float* SE0   = (float*)(sm + EO_SE0);
    float* SE1   = (float*)(sm + EO_SE1);
    float* SA    = (float*)(sm + EO_SA);
    int*   DSTs  = (int*)  (sm + EO_DST);
    float* WEXPs = (float*)(sm + EO_WEXP);

    const int tid  = threadIdx.x;
    const int w    = tid>>5;
    const int lane = tid&31;
    const int nl   = w>>1;         // local node 0..3
    const int sub  = w&1;          // k-half / QK-edge-half
    const int t    = blockIdx.x;
    const int n0   = t*4;
    const int e0   = t*64;
    const int node = n0 + nl;

    // ---- stage: E tile fp32 -> fp16 smem (8 elems / thread-iter), dst, Wexp ----
    for (int i = tid; i < 1024; i += 256) {
        int r = i>>4, c8 = (i&15)*8;
        const float* src = edges + (size_t)(e0+r)*128 + c8;
        float4 v0 = *(const float4*)(src);
        float4 v1 = *(const float4*)(src + 4);
        uint2 p0 = pack_h4(v0), p1 = pack_h4(v1);
        uint4 pk; pk.x = p0.x; pk.y = p0.y; pk.z = p1.x; pk.w = p1.y;
        *(uint4*)(Es + r*128 + c8) = pk;
    }
    if (tid < 64) DSTs[tid] = eidx[NE + e0 + tid];
    if (tid >= 64 && tid < 128) WEXPs[tid-64] = Wexp[tid-64];

    const int h = lane>>2;           // head owned by this lane
    const int q = lane&3;            // quad index

    // ---- P quarter-slice (fp16 -> fp32 regs); Q quad ----
    float4 Pr[4];
    #pragma unroll
    for (int i = 0; i < 4; i++)
        Pr[i] = unpack_h4(*(const uint2*)(g_P + ((size_t)node*8 + h)*128 + q*4 + (sub*4 + i)*16));
    float4 Qr = *(const float4*)(g_Q + (size_t)node*128 + lane*4);
    __syncthreads();

    // ---- scores: partial over sub's k-half; QK(dst) by edge-half owner ----
    float* SEo = sub ? SE1 : SE0;
    #pragma unroll
    for (int e = 0; e < 16; e++) {
        const int row = nl*16 + e;
        const __half* er = Es + row*128;
        float s = 0.f;
        #pragma unroll
        for (int i = 0; i < 4; i++) {
            float4 E4 = unpack_h4(*(const uint2*)(er + q*4 + (sub*4 + i)*16));
            s += E4.x*Pr[i].x + E4.y*Pr[i].y + E4.z*Pr[i].z + E4.w*Pr[i].w;
        }
        if ((e>>3) == sub) {
            int dst = DSTs[row];
            float4 K4 = *(const float4*)(g_KS + (size_t)dst*128 + lane*4);
            s += Qr.x*K4.x + Qr.y*K4.y + Qr.z*K4.z + Qr.w*K4.w;
        }
        s += __shfl_xor_sync(0xffffffffu, s, 1);
        s += __shfl_xor_sync(0xffffffffu, s, 2);
        if (q == 0) SEo[row*8 + h] = s;
    }
    __syncthreads();

    // ---- head expansion SA = (SE0+SE1) @ Wexp ----
    for (int i = tid; i < 512; i += 256) {
        int e = i>>3, he = i&7;
        float v = 0.f;
        #pragma unroll
        for (int hh = 0; hh < 8; hh++)
            v += (SE0[e*8 + hh] + SE1[e*8 + hh])*WEXPs[hh*8 + he];
        SA[i] = v;
    }
    __syncthreads();

    // ---- segment softmax per (node, he) ----
    if (tid < 32) {
        int nd = tid>>3, he = tid&7;
        int base = nd*16;
        float m = -1e30f;
        #pragma unroll
        for (int j = 0; j < 16; j++) m = fmaxf(m, SA[(base+j)*8 + he]);
        float ex[16], su = 0.f;
        #pragma unroll
        for (int j = 0; j < 16; j++) { ex[j] = __expf(SA[(base+j)*8 + he] - m); su += ex[j]; }
        float inv = 1.f/su;
        #pragma unroll
        for (int j = 0; j < 16; j++) SA[(base+j)*8 + he] = ex[j]*inv;
    }
    __syncthreads();

    const int c4 = lane*4;           // lane's 4 consecutive cols / k
    // ---- z for this sub's 4 heads, all 16 edges (fp16 in, fp16 out) ----
    {
        const int hb = sub*4;
        float4 zac[4];
        #pragma unroll
        for (int j = 0; j < 4; j++) zac[j] = make_float4(0.f,0.f,0.f,0.f);
        #pragma unroll
        for (int e = 0; e < 16; e++) {
            const int row = nl*16 + e;
            float4 a4 = *(const float4*)(SA + row*8 + hb);   // broadcast
            float4 E4 = unpack_h4(*(const uint2*)(Es + row*128 + c4)); // 8B, conflict-free
            zac[0].x += a4.x*E4.x; zac[0].y += a4.x*E4.y; zac[0].z += a4.x*E4.z; zac[0].w += a4.x*E4.w;
            zac[1].x += a4.y*E4.x; zac[1].y += a4.y*E4.y; zac[1].z += a4.y*E4.z; zac[1].w += a4.y*E4.w;
            zac[2].x += a4.z*E4.x; zac[2].y += a4.z*E4.y; zac[2].z += a4.z*E4.z; zac[2].w += a4.z*E4.w;
            zac[3].x += a4.w*E4.x; zac[3].y += a4.w*E4.y; zac[3].z += a4.w*E4.z; zac[3].w += a4.w*E4.w;
        }
        #pragma unroll
        for (int j = 0; j < 4; j++)
            *(uint2*)(g_z + (size_t)node*1024 + (hb + j)*128 + c4) = pack_h4(zac[j]);
    }

    // ---- aggv: this sub's 8 edges, all cols (V via LDG, L2-hot); combine via SE0 ----
    const int h2 = lane>>2;
    float4 vacc = make_float4(0.f,0.f,0.f,0.f);
    #pragma unroll
    for (int e = 0; e < 8; e++) {
        const int row = nl*16 + sub*8 + e;
        int dst = DSTs[row];
        float a = SA[row*8 + h2];
        float4 V4 = *(const float4*)(g_V + (size_t)dst*128 + c4);
        vacc.x += a*V4.x; vacc.y += a*V4.y; vacc.z += a*V4.z; vacc.w += a*V4.w;
    }
    float* PS = SE0;   // dead after expansion
    if (sub == 0) *(float4*)(PS + nl*128 + c4) = vacc;
    __syncthreads();
    if (sub == 1) {
        float4 p = *(const float4*)(PS + nl*128 + c4);
        vacc.x += p.x; vacc.y += p.y; vacc.z += p.z; vacc.w += p.w;
        *(float4*)(g_aggv + (size_t)node*128 + c4) = vacc;
    }
}

// ---------------- launch ----------------
extern "C" void kernel_launch(void* const* d_in, const int* in_sizes, int n_in,
                              void* d_out, int out_size)
{
    const float* x    = (const float*)d_in[0];
    const float* edges= (const float*)d_in[1];
    const int*   eidx = (const int*)  d_in[2];
    const float* Wq   = (const float*)d_in[3];
    const float* Wk   = (const float*)d_in[4];
    const float* Wv   = (const float*)d_in[5];
    const float* Wek  = (const float*)d_in[6];
    const float* Wev  = (const float*)d_in[7];
    const float* Wexp = (const float*)d_in[8];
    const float* Wout = (const float*)d_in[9];
    const float* bout = (const float*)d_in[10];
    float* out = (float*)d_out;

    float *Qg, *KSg, *Vg, *aggvg;
    cudaGetSymbolAddress((void**)&Qg,    g_Q);
    cudaGetSymbolAddress((void**)&KSg,   g_KS);
    cudaGetSymbolAddress((void**)&Vg,    g_V);
    cudaGetSymbolAddress((void**)&aggvg, g_aggv);

    cudaFuncSetAttribute(gemm_multi,  cudaFuncAttributeMaxDynamicSharedMemorySize, GEMM_SMEM);
    cudaFuncSetAttribute(pkern,       cudaFuncAttributeMaxDynamicSharedMemorySize, PK_SMEM);
    cudaFuncSetAttribute(ykern,       cudaFuncAttributeMaxDynamicSharedMemorySize, YK_SMEM);
    cudaFuncSetAttribute(edge_kernel, cudaFuncAttributeMaxDynamicSharedMemorySize, EDGE_SMEM);

    // weight prep (4 split slots + WekT transpose in slot 4)
    wsplit_kernel<<<dim3(64,5),256>>>(Wq, Wk, Wv, Wout, Wek);

    // Q / KS / V
    gemm_multi<<<(NN+127)/128,512,GEMM_SMEM>>>(x, 0, 3, Qg, KSg, Vg, nullptr, NN);

    // P[n,h,k]  (64 nodes x 4 heads per block; 4 CTAs/SM)
    pkern<<<dim3((NN+63)/64, 2),512,PK_SMEM>>>();

    // edge pass: scores -> expansion -> softmax -> z + aggv
    edge_kernel<<<NT4,256,EDGE_SMEM>>>(edges, eidx, Wexp);

    // aggv += z @ Wev (block-diagonal)
    ykern<<<(NN+63)/64,512,YK_SMEM>>>(Wev);

    // out = (aggv + y) @ (-Wout) + bout
    gemm_multi<<<(NN+127)/128,512,GEMM_SMEM>>>(aggvg, 3, 1, out, out, out, bout, NN);
}